// round 8
// baseline (speedup 1.0000x reference)
#include <cuda_runtime.h>
#include <cuda_bf16.h>
#include <stdint.h>
#include <math.h>

#define NB   64
#define NQ   900
#define NT   128
#define NCLS 91
#define NSEG 8
#define SEGW 113    // 8*113 = 904 >= 900

typedef unsigned long long u64;
typedef unsigned int       u32;

__device__ __forceinline__ u32 f2ord(float f) {
    u32 u = __float_as_uint(f);
    return (u & 0x80000000u) ? ~u : (u | 0x80000000u);
}
__device__ __forceinline__ u64 umin64(u64 a, u64 b) { return a < b ? a : b; }
__device__ __forceinline__ u32 redux_min(u32 v) {
    u32 r;
    asm("redux.sync.min.u32 %0, %1, 0xffffffff;" : "=r"(r) : "r"(v));
    return r;
}
// exact warp-wide u64 min (keys unique)
__device__ __forceinline__ u64 wredmin(u64 k) {
    u32 hi = (u32)(k >> 32);
    u32 mh = redux_min(hi);
    u32 lo = (hi == mh) ? (u32)k : 0xFFFFFFFFu;
    u32 ml = redux_min(lo);
    return ((u64)mh << 32) | ml;
}

// ---------------------------------------------------------------------------
// Kernel 1: cost matrix (row-major).  8 warps x 2 rows; warp-level softmax.
// ---------------------------------------------------------------------------
__global__ void __launch_bounds__(256) cost_kernel(
    const float* __restrict__ logits,
    const float* __restrict__ pboxes,
    const int*   __restrict__ labels,
    const float* __restrict__ tboxes,
    float* __restrict__ Cout)
{
    const int b    = blockIdx.y;
    const int tid  = threadIdx.x;
    const int lane = tid & 31;
    const int wid  = tid >> 5;

    __shared__ float4 s_tb[NT];
    __shared__ float4 s_tx[NT];
    __shared__ float  s_ta[NT];
    __shared__ int    s_lab[NT];
    __shared__ float  s_exp[8][92];

    if (tid < NT) {
        const float* tb = tboxes + ((size_t)b * NT + tid) * 4;
        float cx = tb[0], cy = tb[1], w = tb[2], h = tb[3];
        s_tb[tid] = make_float4(cx, cy, w, h);
        float x0 = cx - 0.5f * w, y0 = cy - 0.5f * h;
        float x1 = cx + 0.5f * w, y1 = cy + 0.5f * h;
        s_tx[tid] = make_float4(x0, y0, x1, y1);
        s_ta[tid] = (x1 - x0) * (y1 - y0);
        s_lab[tid] = labels[b * NT + tid];
    }
    __syncthreads();

    #pragma unroll
    for (int rr = 0; rr < 2; rr++) {
        int q = blockIdx.x * 16 + rr * 8 + wid;
        if (q >= NQ) continue;

        const float* lr = logits + ((size_t)b * NQ + q) * NCLS;
        float l0 = lr[lane];
        float l1 = lr[lane + 32];
        float l2 = (lane + 64 < NCLS) ? lr[lane + 64] : -INFINITY;
        float m = fmaxf(fmaxf(l0, l1), l2);
        #pragma unroll
        for (int o = 16; o; o >>= 1) m = fmaxf(m, __shfl_xor_sync(0xffffffffu, m, o));
        float e0 = expf(l0 - m), e1 = expf(l1 - m);
        float e2 = (lane + 64 < NCLS) ? expf(l2 - m) : 0.0f;
        float ssum = e0 + e1 + e2;
        #pragma unroll
        for (int o = 16; o; o >>= 1) ssum += __shfl_xor_sync(0xffffffffu, ssum, o);
        s_exp[wid][lane] = e0;
        s_exp[wid][lane + 32] = e1;
        if (lane + 64 < NCLS) s_exp[wid][lane + 64] = e2;
        __syncwarp();
        float inv = 1.0f / ssum;

        const float* pbp = pboxes + ((size_t)b * NQ + q) * 4;
        float pcx = pbp[0], pcy = pbp[1], pw = pbp[2], ph = pbp[3];
        float px0 = pcx - 0.5f * pw, py0 = pcy - 0.5f * ph;
        float px1 = pcx + 0.5f * pw, py1 = pcy + 0.5f * ph;
        float pa  = (px1 - px0) * (py1 - py0);

        float cst[4];
        #pragma unroll
        for (int r = 0; r < 4; r++) {
            int t = (lane << 2) | r;
            float4 tb = s_tb[t];
            float4 tx = s_tx[t];
            float pl  = s_exp[wid][s_lab[t]] * inv;
            float l1c = fabsf(pcx - tb.x) + fabsf(pcy - tb.y)
                      + fabsf(pw - tb.z) + fabsf(ph - tb.w);
            float ix0 = fmaxf(px0, tx.x), iy0 = fmaxf(py0, tx.y);
            float ix1 = fminf(px1, tx.z), iy1 = fminf(py1, tx.w);
            float inter = fmaxf(ix1 - ix0, 0.0f) * fmaxf(iy1 - iy0, 0.0f);
            float uni   = pa + s_ta[t] - inter;
            float iou   = inter / uni;
            float cx0 = fminf(px0, tx.x), cy0 = fminf(py0, tx.y);
            float cx1 = fmaxf(px1, tx.z), cy1 = fmaxf(py1, tx.w);
            float ac  = fmaxf(cx1 - cx0, 0.0f) * fmaxf(cy1 - cy0, 0.0f);
            float giou = iou - (ac - uni) / ac;
            cst[r] = -pl + 5.0f * l1c - 2.0f * giou;
        }

        float* crow = Cout + ((size_t)b * NQ + q) * NT;
        *(float4*)(crow + (lane << 2)) = make_float4(cst[0], cst[1], cst[2], cst[3]);
    }
}

// ---------------------------------------------------------------------------
// Kernel 2: greedy.  256 threads build per-(segment,column) top-3 tables;
// warp 0 then runs the 128 sequential steps barrier-free.
// key = (f2ord(v)<<18) | (q<<8) | c  == flattened row-major argmin order.
// ---------------------------------------------------------------------------
__global__ void __launch_bounds__(256) greedy_kernel(
    const float* __restrict__ Cmat,
    float* __restrict__ out)
{
    const int b    = blockIdx.x;
    const int tid  = threadIdx.x;
    const int lane = tid & 31;
    const int wid  = tid >> 5;
    const float* __restrict__ Cb = Cmat + (size_t)b * NQ * NT;

    __shared__ u64 seg1[NSEG][NT];
    __shared__ u64 seg2[NSEG][NT];
    __shared__ u64 seg3[NSEG][NT];
    __shared__ u32 rowdead[32];
    __shared__ int s_src[NT], s_tgt[NT];

    // ---- init: top-3 of each (segment, column); coalesced row-major reads ----
    {
        const int c    = tid & 127;
        const int half = tid >> 7;
        for (int sp = 0; sp < NSEG / 2; sp++) {
            const int s  = half * (NSEG / 2) + sp;
            const int qa = s * SEGW;
            const int qb = (qa + SEGW < NQ) ? qa + SEGW : NQ;
            u64 m1 = ~0ull, m2 = ~0ull, m3 = ~0ull;

            auto ins = [&](float v, int q) {
                u64 k = ((u64)f2ord(v) << 18) | ((u32)q << 8) | (u32)c;
                if (k < m3) {
                    if (k < m1)      { m3 = m2; m2 = m1; m1 = k; }
                    else if (k < m2) { m3 = m2; m2 = k; }
                    else             { m3 = k; }
                }
            };

            int q = qa;
            for (; q + 4 <= qb; q += 4) {
                float v0 = Cb[(q + 0) * NT + c];
                float v1 = Cb[(q + 1) * NT + c];
                float v2 = Cb[(q + 2) * NT + c];
                float v3 = Cb[(q + 3) * NT + c];
                ins(v0, q + 0); ins(v1, q + 1); ins(v2, q + 2); ins(v3, q + 3);
            }
            for (; q < qb; q++) ins(Cb[q * NT + c], q);

            seg1[s][c] = m1; seg2[s][c] = m2; seg3[s][c] = m3;
        }
    }
    if (tid < 32) rowdead[tid] = 0u;
    __syncthreads();

    if (wid != 0) return;

    // ---- warp 0: register-resident column keys ----
    u64 ck[4];
    #pragma unroll
    for (int r = 0; r < 4; r++) {
        const int c = r * 32 + lane;
        u64 m = ~0ull;
        #pragma unroll
        for (int s = 0; s < NSEG; s++) m = umin64(m, seg1[s][c]);
        ck[r] = m;
    }

    for (int t = 0; t < NT; t++) {
        u64 h = umin64(umin64(ck[0], ck[1]), umin64(ck[2], ck[3]));
        u64 m = wredmin(h);
        const int i = (int)((m >> 8) & 0x3FFu);
        const int j = (int)(m & 0xFFu);
        if (lane == 0) {
            s_src[t] = i;
            s_tgt[t] = j;
            rowdead[i >> 5] |= (1u << (i & 31));
        }
        __syncwarp();
        if (t == NT - 1) break;

        const int si = i / SEGW;

        u32 resc = 0;
        #pragma unroll
        for (int r = 0; r < 4; r++) {
            if (ck[r] == m) { ck[r] = ~0ull; continue; }   // matched column j
            if (ck[r] == ~0ull) continue;                  // already matched
            const int c = r * 32 + lane;
            u64 k1 = seg1[si][c];
            if (k1 == ~0ull || (int)((k1 >> 8) & 0x3FFu) != i) continue;  // not dirty

            // promote from cached spares (bitmap includes i already)
            u64 k2 = seg2[si][c], k3 = seg3[si][c];
            bool a2 = false, a3 = false;
            if (k2 != ~0ull) { int q2 = (int)((k2 >> 8) & 0x3FFu); a2 = !((rowdead[q2 >> 5] >> (q2 & 31)) & 1u); }
            if (k3 != ~0ull) { int q3 = (int)((k3 >> 8) & 0x3FFu); a3 = !((rowdead[q3 >> 5] >> (q3 & 31)) & 1u); }
            if (a2) {
                seg1[si][c] = k2;
                seg2[si][c] = a3 ? k3 : ~0ull;
                seg3[si][c] = ~0ull;
            } else if (a3) {
                seg1[si][c] = k3;
                seg2[si][c] = ~0ull;
                seg3[si][c] = ~0ull;
            } else {
                resc |= (1u << r);
                continue;
            }
            u64 nk = ~0ull;
            #pragma unroll
            for (int s = 0; s < NSEG; s++) nk = umin64(nk, seg1[s][c]);
            ck[r] = nk;
        }

        // rare: both spares dead -> warp-cooperative segment rescan (top-3)
        if (__ballot_sync(0xffffffffu, resc != 0)) {
            const int qa = si * SEGW;
            const int qb = (qa + SEGW < NQ) ? qa + SEGW : NQ;
            #pragma unroll
            for (int r = 0; r < 4; r++) {
                u32 mask = __ballot_sync(0xffffffffu, (resc >> r) & 1u);
                while (mask) {
                    const int sl = __ffs(mask) - 1;
                    mask &= mask - 1;
                    const int c2 = r * 32 + sl;
                    u64 l1 = ~0ull, l2 = ~0ull, l3 = ~0ull;
                    for (int q = qa + lane; q < qb; q += 32) {
                        if ((rowdead[q >> 5] >> (q & 31)) & 1u) continue;
                        float v = Cb[q * NT + c2];
                        u64 k = ((u64)f2ord(v) << 18) | ((u32)q << 8) | (u32)c2;
                        if (k < l3) {
                            if (k < l1)      { l3 = l2; l2 = l1; l1 = k; }
                            else if (k < l2) { l3 = l2; l2 = k; }
                            else             { l3 = k; }
                        }
                    }
                    u64 g1 = wredmin(l1);
                    if (l1 == g1) { l1 = l2; l2 = l3; l3 = ~0ull; }
                    u64 g2 = wredmin(l1);
                    if (l1 == g2) { l1 = l2; l2 = l3; l3 = ~0ull; }
                    u64 g3 = wredmin(l1);
                    if (lane == sl) {
                        seg1[si][c2] = g1;
                        seg2[si][c2] = g2;
                        seg3[si][c2] = g3;
                        u64 nk = ~0ull;
                        #pragma unroll
                        for (int s = 0; s < NSEG; s++) nk = umin64(nk, seg1[s][c2]);
                        ck[r] = nk;
                    }
                }
            }
        }
        __syncwarp();
    }

    __syncwarp();
    #pragma unroll
    for (int r = 0; r < 4; r++) {
        int t = r * 32 + lane;
        out[b * NT + t]           = (float)s_src[t];
        out[NB * NT + b * NT + t] = (float)s_tgt[t];
    }
}

// ---------------------------------------------------------------------------
extern "C" void kernel_launch(void* const* d_in, const int* in_sizes, int n_in,
                              void* d_out, int out_size) {
    const float* logits = (const float*)d_in[0];
    const float* pboxes = (const float*)d_in[1];
    const int*   labels = (const int*)d_in[2];
    const float* tboxes = (const float*)d_in[3];
    float* out = (float*)d_out;

    float* Cout = out + 2 * NB * NT;

    dim3 grid1((NQ + 15) / 16, NB);
    cost_kernel<<<grid1, 256>>>(logits, pboxes, labels, tboxes, Cout);
    greedy_kernel<<<NB, 256>>>(Cout, out);
}